// round 2
// baseline (speedup 1.0000x reference)
#include <cuda_runtime.h>
#include <math.h>

#define FULL_MASK 0xffffffffu
#define MAX_B 4096
#define DLEV 5

// Scratch (device-global: allocation inside kernel_launch is forbidden)
__device__ float g_row_total[MAX_B];
__device__ unsigned int g_block_count = 0;   // reset by last block each launch -> graph-replay safe

__global__ void hier_loss_fused_kernel(
    const float* __restrict__ y_pred,
    const float* __restrict__ y_true,
    const float* __restrict__ class_weights,
    const int*   __restrict__ path_ids,   // [C, D]
    const int*   __restrict__ path_len,   // [C]
    const int*   __restrict__ sib_start,  // [C, D]
    const int*   __restrict__ sib_size,   // [C, D]
    float* __restrict__ out,
    int B, int C)
{
    const int warp = threadIdx.x >> 5;
    const int lane = threadIdx.x & 31;
    const int warps_per_block = blockDim.x >> 5;
    const int row = blockIdx.x * warps_per_block + warp;

    if (row < B) {
        const float* prow = y_pred + (size_t)row * C;
        const float* trow = y_true + (size_t)row * C;

        // ---- fused dual argmax over C (float4 vectorized, first-index tiebreak) ----
        float pv = -INFINITY, tv = -INFINITY;
        int   pi = 0,          ti = 0;

        const int n4 = C >> 2;  // 682 for C=2728
        const float4* p4 = reinterpret_cast<const float4*>(prow);
        const float4* t4 = reinterpret_cast<const float4*>(trow);

        for (int i = lane; i < n4; i += 32) {
            float4 a = p4[i];
            float4 b = t4[i];
            int base = i << 2;
            if (a.x > pv) { pv = a.x; pi = base;     }
            if (a.y > pv) { pv = a.y; pi = base + 1; }
            if (a.z > pv) { pv = a.z; pi = base + 2; }
            if (a.w > pv) { pv = a.w; pi = base + 3; }
            if (b.x > tv) { tv = b.x; ti = base;     }
            if (b.y > tv) { tv = b.y; ti = base + 1; }
            if (b.z > tv) { tv = b.z; ti = base + 2; }
            if (b.w > tv) { tv = b.w; ti = base + 3; }
        }
        for (int c = (n4 << 2) + lane; c < C; c += 32) {
            float a = prow[c];
            float b = trow[c];
            if (a > pv) { pv = a; pi = c; }
            if (b > tv) { tv = b; ti = c; }
        }

        // warp reduce: max value, lowest index on ties
        #pragma unroll
        for (int off = 16; off > 0; off >>= 1) {
            float opv = __shfl_down_sync(FULL_MASK, pv, off);
            int   opi = __shfl_down_sync(FULL_MASK, pi, off);
            if (opv > pv || (opv == pv && opi < pi)) { pv = opv; pi = opi; }
            float otv = __shfl_down_sync(FULL_MASK, tv, off);
            int   oti = __shfl_down_sync(FULL_MASK, ti, off);
            if (otv > tv || (otv == tv && oti < ti)) { tv = otv; ti = oti; }
        }

        if (lane == 0) {
            const int pred_top = pi;
            const int true_top = ti;
            const int len_p = path_len[pred_top];
            const int len_t = path_len[true_top];
            const int lmin  = (len_p < len_t) ? len_p : len_t;

            float total = 0.0f;
            const int diff = (len_p > len_t) ? (len_p - len_t) : (len_t - len_p);

            if (diff != 0) {   // otherwise total is exactly 0
                float local = 0.0f;
                #pragma unroll
                for (int l = 0; l < DLEV; l++) {
                    if (l < lmin) {
                        const int start = sib_start[true_top * DLEV + l];
                        const int size  = sib_size [true_top * DLEV + l];
                        const int tid_l = path_ids [true_top * DLEV + l];

                        // lse of (y_pred * 0/1 mask): masked-out classes contribute exp(0)=1
                        float s = (float)(C - size);
                        for (int c = start; c < start + size; c++) {
                            s += expf(prow[c]);
                        }
                        const float lse = logf(s);
                        const float ce  = lse - prow[tid_l];
                        const float h   = (float)(len_t - l - 1);
                        local += expf(-0.5f * h) * ce;
                    }
                }
                total = local * (1.5f * (float)diff) * class_weights[true_top];
            }
            g_row_total[row] = total;
        }
    }

    // ---- grid-wide deterministic reduction: last block sums everything ----
    __shared__ bool s_is_last;
    __threadfence();                        // make g_row_total writes visible grid-wide
    __syncthreads();                        // all warps in this block done writing
    if (threadIdx.x == 0) {
        unsigned int done = atomicAdd(&g_block_count, 1u);
        s_is_last = (done == gridDim.x - 1);
    }
    __syncthreads();

    if (s_is_last) {
        __shared__ float s_sum[32];
        float sum = 0.0f;
        for (int i = threadIdx.x; i < B; i += blockDim.x)
            sum += g_row_total[i];           // hot in L2
        #pragma unroll
        for (int off = 16; off > 0; off >>= 1)
            sum += __shfl_down_sync(FULL_MASK, sum, off);
        if (lane == 0) s_sum[warp] = sum;
        __syncthreads();
        if (warp == 0) {
            float v = (lane < warps_per_block) ? s_sum[lane] : 0.0f;
            #pragma unroll
            for (int off = 16; off > 0; off >>= 1)
                v += __shfl_down_sync(FULL_MASK, v, off);
            if (lane == 0) {
                out[0] = v / (float)B;
                g_block_count = 0;           // reset for next graph replay
            }
        }
    }
}

extern "C" void kernel_launch(void* const* d_in, const int* in_sizes, int n_in,
                              void* d_out, int out_size)
{
    const float* y_pred        = (const float*)d_in[0];
    const float* y_true        = (const float*)d_in[1];
    const float* class_weights = (const float*)d_in[2];
    const int*   path_ids      = (const int*)  d_in[3];
    const int*   path_len      = (const int*)  d_in[4];
    const int*   sib_start     = (const int*)  d_in[5];
    const int*   sib_size      = (const int*)  d_in[6];

    const int C = in_sizes[2];            // 2728
    const int B = in_sizes[0] / C;        // 4096

    const int threads = 256;              // 8 warps = 8 rows per block
    const int rows_per_block = threads / 32;
    const int blocks = (B + rows_per_block - 1) / rows_per_block;   // 512

    hier_loss_fused_kernel<<<blocks, threads>>>(
        y_pred, y_true, class_weights, path_ids, path_len, sib_start, sib_size,
        (float*)d_out, B, C);
}

// round 3
// speedup vs baseline: 1.0763x; 1.0763x over previous
#include <cuda_runtime.h>
#include <math.h>

#define FULL_MASK 0xffffffffu
#define MAX_B 4096
#define DLEV 5

// Scratch (device allocation is forbidden; __device__ globals are the sanctioned path)
__device__ float g_row_total[MAX_B];
__device__ unsigned int g_block_count = 0;   // reset by last block each launch -> graph-replay safe

// first-index tie-break within a slot: indices increase monotonically, strict > keeps earliest
#define UPD4(V, I, Q, BASE)                           \
    do {                                              \
        if ((Q).x > (V)) { (V) = (Q).x; (I) = (BASE);     } \
        if ((Q).y > (V)) { (V) = (Q).y; (I) = (BASE) + 1; } \
        if ((Q).z > (V)) { (V) = (Q).z; (I) = (BASE) + 2; } \
        if ((Q).w > (V)) { (V) = (Q).w; (I) = (BASE) + 3; } \
    } while (0)

// merge two trackers, lowest index wins ties
#define MRG(V, I, V2, I2)                                     \
    do {                                                      \
        if ((V2) > (V) || ((V2) == (V) && (I2) < (I))) {      \
            (V) = (V2); (I) = (I2);                           \
        }                                                     \
    } while (0)

__global__ void __launch_bounds__(256)
hier_loss_fused_kernel(
    const float* __restrict__ y_pred,
    const float* __restrict__ y_true,
    const float* __restrict__ class_weights,
    const int*   __restrict__ path_ids,   // [C, D]
    const int*   __restrict__ path_len,   // [C]
    const int*   __restrict__ sib_start,  // [C, D]
    const int*   __restrict__ sib_size,   // [C, D]
    float* __restrict__ out,
    int B, int C)
{
    const int warp = threadIdx.x >> 5;
    const int lane = threadIdx.x & 31;
    const int warps_per_block = blockDim.x >> 5;
    const int row = blockIdx.x * warps_per_block + warp;

    if (row < B) {
        const float* prow = y_pred + (size_t)row * C;
        const float* trow = y_true + (size_t)row * C;

        const int n4 = C >> 2;  // 682 for C=2728
        const float4* p4 = reinterpret_cast<const float4*>(prow);
        const float4* t4 = reinterpret_cast<const float4*>(trow);

        // 4 independent trackers per tensor -> short compare chains, batched loads
        float pv0 = -INFINITY, pv1 = -INFINITY, pv2 = -INFINITY, pv3 = -INFINITY;
        float tv0 = -INFINITY, tv1 = -INFINITY, tv2 = -INFINITY, tv3 = -INFINITY;
        int   pi0 = 0, pi1 = 0, pi2 = 0, pi3 = 0;
        int   ti0 = 0, ti1 = 0, ti2 = 0, ti3 = 0;

        int i = lane;
        // unrolled x4: 8 independent 16B loads issued before any compare (MLP ~8/lane)
        for (; i + 96 < n4; i += 128) {
            float4 a0 = p4[i];
            float4 a1 = p4[i + 32];
            float4 a2 = p4[i + 64];
            float4 a3 = p4[i + 96];
            float4 b0 = t4[i];
            float4 b1 = t4[i + 32];
            float4 b2 = t4[i + 64];
            float4 b3 = t4[i + 96];
            UPD4(pv0, pi0, a0,  i        << 2);
            UPD4(pv1, pi1, a1, (i + 32)  << 2);
            UPD4(pv2, pi2, a2, (i + 64)  << 2);
            UPD4(pv3, pi3, a3, (i + 96)  << 2);
            UPD4(tv0, ti0, b0,  i        << 2);
            UPD4(tv1, ti1, b1, (i + 32)  << 2);
            UPD4(tv2, ti2, b2, (i + 64)  << 2);
            UPD4(tv3, ti3, b3, (i + 96)  << 2);
        }
        // float4 remainder
        for (; i < n4; i += 32) {
            float4 a = p4[i];
            float4 b = t4[i];
            UPD4(pv0, pi0, a, i << 2);
            UPD4(tv0, ti0, b, i << 2);
        }
        // scalar remainder (none for C=2728; kept for generality)
        for (int c = (n4 << 2) + lane; c < C; c += 32) {
            float a = prow[c];
            float b = trow[c];
            if (a > pv0) { pv0 = a; pi0 = c; }
            if (b > tv0) { tv0 = b; ti0 = c; }
        }

        // merge slot trackers (tie -> lowest index)
        MRG(pv0, pi0, pv1, pi1);
        MRG(pv2, pi2, pv3, pi3);
        MRG(pv0, pi0, pv2, pi2);
        MRG(tv0, ti0, tv1, ti1);
        MRG(tv2, ti2, tv3, ti3);
        MRG(tv0, ti0, tv2, ti2);

        // warp reduce: max value, lowest index on ties
        float pv = pv0, tv = tv0;
        int   pi = pi0, ti = ti0;
        #pragma unroll
        for (int off = 16; off > 0; off >>= 1) {
            float opv = __shfl_down_sync(FULL_MASK, pv, off);
            int   opi = __shfl_down_sync(FULL_MASK, pi, off);
            MRG(pv, pi, opv, opi);
            float otv = __shfl_down_sync(FULL_MASK, tv, off);
            int   oti = __shfl_down_sync(FULL_MASK, ti, off);
            MRG(tv, ti, otv, oti);
        }

        if (lane == 0) {
            const int pred_top = pi;
            const int true_top = ti;
            const int len_p = path_len[pred_top];
            const int len_t = path_len[true_top];
            const int lmin  = (len_p < len_t) ? len_p : len_t;

            float total = 0.0f;
            const int diff = (len_p > len_t) ? (len_p - len_t) : (len_t - len_p);

            if (diff != 0) {   // otherwise total is exactly 0
                float local = 0.0f;
                #pragma unroll
                for (int l = 0; l < DLEV; l++) {
                    if (l < lmin) {
                        const int start = sib_start[true_top * DLEV + l];
                        const int size  = sib_size [true_top * DLEV + l];
                        const int tid_l = path_ids [true_top * DLEV + l];

                        // lse of (y_pred * 0/1 mask): masked-out classes contribute exp(0)=1
                        float s = (float)(C - size);
                        for (int c = start; c < start + size; c++) {
                            s += expf(prow[c]);
                        }
                        const float lse = logf(s);
                        const float ce  = lse - prow[tid_l];
                        const float h   = (float)(len_t - l - 1);
                        local += expf(-0.5f * h) * ce;
                    }
                }
                total = local * (1.5f * (float)diff) * class_weights[true_top];
            }
            g_row_total[row] = total;
        }
    }

    // ---- grid-wide deterministic reduction: last block sums everything ----
    __shared__ bool s_is_last;
    __syncthreads();                          // block writes happen-before thread 0's fence
    if (threadIdx.x == 0) {
        __threadfence();                      // release g_row_total grid-wide (thread 0 only)
        unsigned int done = atomicAdd(&g_block_count, 1u);
        s_is_last = (done == gridDim.x - 1);
    }
    __syncthreads();

    if (s_is_last) {
        __shared__ float s_sum[32];
        float sum = 0.0f;
        for (int idx = threadIdx.x; idx < B; idx += blockDim.x)
            sum += g_row_total[idx];          // hot in L2
        #pragma unroll
        for (int off = 16; off > 0; off >>= 1)
            sum += __shfl_down_sync(FULL_MASK, sum, off);
        if (lane == 0) s_sum[warp] = sum;
        __syncthreads();
        if (warp == 0) {
            float v = (lane < warps_per_block) ? s_sum[lane] : 0.0f;
            #pragma unroll
            for (int off = 16; off > 0; off >>= 1)
                v += __shfl_down_sync(FULL_MASK, v, off);
            if (lane == 0) {
                out[0] = v / (float)B;
                g_block_count = 0;            // reset for next graph replay
            }
        }
    }
}

extern "C" void kernel_launch(void* const* d_in, const int* in_sizes, int n_in,
                              void* d_out, int out_size)
{
    const float* y_pred        = (const float*)d_in[0];
    const float* y_true        = (const float*)d_in[1];
    const float* class_weights = (const float*)d_in[2];
    const int*   path_ids      = (const int*)  d_in[3];
    const int*   path_len      = (const int*)  d_in[4];
    const int*   sib_start     = (const int*)  d_in[5];
    const int*   sib_size      = (const int*)  d_in[6];

    const int C = in_sizes[2];            // 2728
    const int B = in_sizes[0] / C;        // 4096

    const int threads = 256;              // 8 warps = 8 rows per block
    const int rows_per_block = threads / 32;
    const int blocks = (B + rows_per_block - 1) / rows_per_block;   // 512

    hier_loss_fused_kernel<<<blocks, threads>>>(
        y_pred, y_true, class_weights, path_ids, path_len, sib_start, sib_size,
        (float*)d_out, B, C);
}